// round 14
// baseline (speedup 1.0000x reference)
#include <cuda_runtime.h>
#include <cstdint>

// ---------------- problem constants ----------------
#define B      128
#define D      768
#define POOL   100
#define LG     6
#define LE     6
#define GLEN   5
#define ELEN   20
#define H      12
#define HD     64
#define TOPK   5

// Output rows: one row = HD floats = 16 float4 = 256 bytes.
#define G_ROWS     (LG*2*B*H*GLEN)              // 92,160
#define E_ROWS     (LE*2*B*H*(TOPK*ELEN))       // 1,843,200
#define G_PAIRS    (G_ROWS*8)                   // 737,280

#define THREADS    256
#define G_BLOCKS   (G_PAIRS/THREADS)            // 2,880 (exact)
#define E_BLOCKS   (12*H*POOL)                  // 14,400  (ld,h,p)
#define TOTAL_BLOCKS (G_BLOCKS + E_BLOCKS)      // 17,280

#define MAXENT     (B*TOPK)                     // 640

// scratch (no cudaMalloc allowed)
__device__ int d_pcount[POOL];                  // reset via cudaMemsetAsync
__device__ int d_plist[POOL * MAXENT];          // packed (b<<3)|k entries

// ---------------------------------------------------------------------------
// Kernel 1: cosine-sim + top-5 selection (proven variant) + inverse-list
// build. qn dropped (positive per-row constant => ranking invariant);
// tie-break = lowest index (jax.lax.top_k order). For each selected (b,k,p)
// we append (b<<3)|k to p's list. List order is atomic-race dependent but
// the output is order-independent (each entry owns distinct rows).
// ---------------------------------------------------------------------------
__global__ __launch_bounds__(512) void select_topk_kernel(
        const float4* __restrict__ query4,
        const float4* __restrict__ keys4) {
    const int b    = blockIdx.x;
    const int t    = threadIdx.x;
    const int warp = t >> 5;
    const int lane = t & 31;

    __shared__ float sims[POOL];

    const float4* qr = query4 + (size_t)b * (D / 4);
    float4 fq[6];
    #pragma unroll
    for (int j = 0; j < 6; j++) fq[j] = __ldg(&qr[lane + 32 * j]);

    for (int p = warp; p < POOL; p += 16) {
        const float4* kr = keys4 + (size_t)p * (D / 4);
        float dot = 0.f, kk = 0.f;
        #pragma unroll
        for (int j = 0; j < 6; j++) {
            float4 kv = __ldg(&kr[lane + 32 * j]);
            dot = fmaf(fq[j].x, kv.x, dot);
            dot = fmaf(fq[j].y, kv.y, dot);
            dot = fmaf(fq[j].z, kv.z, dot);
            dot = fmaf(fq[j].w, kv.w, dot);
            kk  = fmaf(kv.x, kv.x, kk);
            kk  = fmaf(kv.y, kv.y, kk);
            kk  = fmaf(kv.z, kv.z, kk);
            kk  = fmaf(kv.w, kv.w, kk);
        }
        #pragma unroll
        for (int o = 16; o > 0; o >>= 1) {
            dot += __shfl_xor_sync(0xFFFFFFFFu, dot, o);
            kk  += __shfl_xor_sync(0xFFFFFFFFu, kk,  o);
        }
        if (lane == 0) {
            float kn = fmaxf(sqrtf(kk), 1e-12f);
            sims[p] = dot / kn;
        }
    }
    __syncthreads();

    if (warp == 0) {
        #pragma unroll
        for (int k = 0; k < TOPK; k++) {
            float best = -3.0e38f;
            int   bi   = POOL;
            #pragma unroll
            for (int j = 0; j < 4; j++) {
                int p = lane + 32 * j;
                if (p < POOL) {
                    float v = sims[p];
                    if (v > best) { best = v; bi = p; }
                }
            }
            #pragma unroll
            for (int o = 16; o > 0; o >>= 1) {
                float ov = __shfl_xor_sync(0xFFFFFFFFu, best, o);
                int   oi = __shfl_xor_sync(0xFFFFFFFFu, bi,   o);
                if (ov > best || (ov == best && oi < bi)) { best = ov; bi = oi; }
            }
            if (lane == 0) {
                int slot = atomicAdd(&d_pcount[bi], 1);
                d_plist[bi * MAXENT + slot] = (b << 3) | k;
                sims[bi] = -3.0e38f;
            }
            __syncwarp();
        }
    }
}

// ---------------------------------------------------------------------------
// Kernel 2: writer, inverse-gather formulation.
//  blocks [0, 2880):      g region, R4 pattern.
//  blocks [2880, 17280):  one block per (ld,h,p). Loads pool[p,ld,:,h,:]
//    (20 rows = 5KB) into smem ONCE, then each warp writes one list entry's
//    20 CONTIGUOUS output rows (5KB linear chunk, 512B per STG).
//    LTS reads: 472MB -> 74MB; writes keep 5KB DRAM page locality.
// ---------------------------------------------------------------------------
__global__ __launch_bounds__(THREADS) void write_out_kernel(
        const float4* __restrict__ g4,
        const float4* __restrict__ pool4,
        float4* __restrict__ out4) {
    const int blk = blockIdx.x;
    const int tid = threadIdx.x;

    if (blk < G_BLOCKS) {
        // ===== g region: out[ld,b,h,gl,:] = g_prompt[ld,gl,h,:] =====
        int gid = blk * THREADS + tid;         // < G_PAIRS exact
        const int c4h = gid & 7;
        const int row = gid >> 3;
        int v  = row;
        int gl = v % GLEN; v /= GLEN;
        int h  = v % H;    v /= H;
        v >>= 7;                               // drop b
        int ld = v;                            // 0..11
        const float4* src = &g4[(((ld * GLEN + gl) * H + h) << 4) + c4h];
        float4 v0 = __ldg(src);
        float4 v1 = __ldg(src + 8);
        float4* dst = out4 + ((long long)row << 4) + c4h;
        __stcs(dst,     v0);
        __stcs(dst + 8, v1);
        return;
    }

    // ===== e block: (ld, h, p) =====
    int eb = blk - G_BLOCKS;                   // 0..14399
    const int p  = eb % POOL;  eb /= POOL;
    const int h  = eb % H;     eb /= H;
    const int ld = eb;                          // 0..11

    const int count = d_pcount[p];             // uniform across block
    if (count == 0) return;

    // load pool[p,ld,e,h,:] for e=0..19 -> 320 float4 (5KB)
    __shared__ float4 s_rows[ELEN * 16];
    // pool float4 layout: [POOL, 12, ELEN, H, 16]
    for (int i = tid; i < ELEN * 16; i += THREADS) {
        const int e = i >> 4;
        const int c = i & 15;
        s_rows[i] = __ldg(&pool4[((((p * 12 + ld) * ELEN + e) * H + h) << 4) + c]);
    }
    __syncthreads();

    const int warp = tid >> 5;
    const int lane = tid & 31;

    // each warp handles one (b,k) entry: 20 contiguous rows = 320 float4
    for (int i = warp; i < count; i += 8) {
        const int entry = d_plist[p * MAXENT + i];
        const int b = entry >> 3;
        const int k = entry & 7;
        // out row base = G_ROWS + ((ld*B + b)*H + h)*100 + k*ELEN
        const long long orow =
            (long long)G_ROWS + (((long long)(ld * B + b) * H + h) * 100 + k * ELEN);
        float4* dst = out4 + (orow << 4);
        #pragma unroll
        for (int j = 0; j < 10; j++) {
            __stcs(dst + lane + 32 * j, s_rows[lane + 32 * j]);
        }
    }
}

// ---------------------------------------------------------------------------
extern "C" void kernel_launch(void* const* d_in, const int* in_sizes, int n_in,
                              void* d_out, int out_size) {
    const float* query = (const float*)d_in[0];
    const float* gprm  = (const float*)d_in[1];
    const float* pool  = (const float*)d_in[2];
    const float* keys  = (const float*)d_in[3];
    float* out = (float*)d_out;

    // reset per-p counters (graph-capturable memset node)
    void* cnt_addr = nullptr;
    cudaGetSymbolAddress(&cnt_addr, d_pcount);
    cudaMemsetAsync(cnt_addr, 0, POOL * sizeof(int));

    // 1. top-k selection + inverse-list build
    select_topk_kernel<<<B, 512>>>((const float4*)query, (const float4*)keys);

    // 2. writer (g blocks + inverse-gather e blocks)
    write_out_kernel<<<TOTAL_BLOCKS, THREADS>>>((const float4*)gprm,
                                                (const float4*)pool,
                                                (float4*)out);
}

// round 15
// speedup vs baseline: 1.0065x; 1.0065x over previous
#include <cuda_runtime.h>
#include <cstdint>

// ---------------- problem constants ----------------
#define B      128
#define D      768
#define POOL   100
#define LG     6
#define LE     6
#define GLEN   5
#define ELEN   20
#define H      12
#define HD     64
#define TOPK   5

// Output rows: one row = HD floats = 16 float4 = 256 bytes.
#define G_ROWS     (LG*2*B*H*GLEN)              // 92,160
#define E_ROWS     (LE*2*B*H*(TOPK*ELEN))       // 1,843,200
#define G_PAIRS    (G_ROWS*8)                   // 737,280

#define THREADS    256
#define G_BLOCKS   (G_PAIRS/THREADS)            // 2,880 (exact)
#define E_BLOCKS   (12*H*POOL)                  // 14,400  (ld,h,p)
#define TOTAL_BLOCKS (G_BLOCKS + E_BLOCKS)      // 17,280

#define MAXENT     (B*TOPK)                     // 640 (list capacity; count<=128)
#define CHUNK_BYTES (ELEN*HD*4)                 // 5120 B contiguous per entry

// scratch (no cudaMalloc allowed)
__device__ int d_pcount[POOL];                  // reset via cudaMemsetAsync
__device__ int d_plist[POOL * MAXENT];          // packed (b<<3)|k entries

// ---------------------------------------------------------------------------
// Kernel 1: cosine-sim + top-5 selection + inverse-list build (R14 variant).
// qn dropped (positive per-row constant => ranking invariant); tie-break =
// lowest index (jax.lax.top_k order). Appends (b<<3)|k to the selected p's
// list; list order is race-dependent but output is order-independent.
// ---------------------------------------------------------------------------
__global__ __launch_bounds__(512) void select_topk_kernel(
        const float4* __restrict__ query4,
        const float4* __restrict__ keys4) {
    const int b    = blockIdx.x;
    const int t    = threadIdx.x;
    const int warp = t >> 5;
    const int lane = t & 31;

    __shared__ float sims[POOL];

    const float4* qr = query4 + (size_t)b * (D / 4);
    float4 fq[6];
    #pragma unroll
    for (int j = 0; j < 6; j++) fq[j] = __ldg(&qr[lane + 32 * j]);

    for (int p = warp; p < POOL; p += 16) {
        const float4* kr = keys4 + (size_t)p * (D / 4);
        float dot = 0.f, kk = 0.f;
        #pragma unroll
        for (int j = 0; j < 6; j++) {
            float4 kv = __ldg(&kr[lane + 32 * j]);
            dot = fmaf(fq[j].x, kv.x, dot);
            dot = fmaf(fq[j].y, kv.y, dot);
            dot = fmaf(fq[j].z, kv.z, dot);
            dot = fmaf(fq[j].w, kv.w, dot);
            kk  = fmaf(kv.x, kv.x, kk);
            kk  = fmaf(kv.y, kv.y, kk);
            kk  = fmaf(kv.z, kv.z, kk);
            kk  = fmaf(kv.w, kv.w, kk);
        }
        #pragma unroll
        for (int o = 16; o > 0; o >>= 1) {
            dot += __shfl_xor_sync(0xFFFFFFFFu, dot, o);
            kk  += __shfl_xor_sync(0xFFFFFFFFu, kk,  o);
        }
        if (lane == 0) {
            float kn = fmaxf(sqrtf(kk), 1e-12f);
            sims[p] = dot / kn;
        }
    }
    __syncthreads();

    if (warp == 0) {
        #pragma unroll
        for (int k = 0; k < TOPK; k++) {
            float best = -3.0e38f;
            int   bi   = POOL;
            #pragma unroll
            for (int j = 0; j < 4; j++) {
                int p = lane + 32 * j;
                if (p < POOL) {
                    float v = sims[p];
                    if (v > best) { best = v; bi = p; }
                }
            }
            #pragma unroll
            for (int o = 16; o > 0; o >>= 1) {
                float ov = __shfl_xor_sync(0xFFFFFFFFu, best, o);
                int   oi = __shfl_xor_sync(0xFFFFFFFFu, bi,   o);
                if (ov > best || (ov == best && oi < bi)) { best = ov; bi = oi; }
            }
            if (lane == 0) {
                int slot = atomicAdd(&d_pcount[bi], 1);
                d_plist[bi * MAXENT + slot] = (b << 3) | k;
                sims[bi] = -3.0e38f;
            }
            __syncwarp();
        }
    }
}

// ---------------------------------------------------------------------------
// Kernel 2: writer with TMA BULK STORES for the e region.
//  blocks [0, 2880):      g region, R4 STG pattern (5% of bytes).
//  blocks [2880, 17280):  one block per (ld,h,p). Loads pool[p,ld,:,h,:]
//    (5KB) into smem once; then each thread tid<count issues ONE
//    cp.async.bulk (5120B smem->gmem) for its entry's CONTIGUOUS output
//    chunk. The TMA engine drives the write stream — no per-lane STG, no
//    L1 wavefront cost, freeing the DRAM write path from the SM store
//    bottleneck. Each issuing thread commits+waits its own bulk group
//    (wait_group.read: smem read completion) before exiting.
// ---------------------------------------------------------------------------
__global__ __launch_bounds__(THREADS) void write_out_kernel(
        const float4* __restrict__ g4,
        const float4* __restrict__ pool4,
        float4* __restrict__ out4) {
    const int blk = blockIdx.x;
    const int tid = threadIdx.x;

    if (blk < G_BLOCKS) {
        // ===== g region: out[ld,b,h,gl,:] = g_prompt[ld,gl,h,:] =====
        int gid = blk * THREADS + tid;         // < G_PAIRS exact
        const int c4h = gid & 7;
        const int row = gid >> 3;
        int v  = row;
        int gl = v % GLEN; v /= GLEN;
        int h  = v % H;    v /= H;
        v >>= 7;                               // drop b
        int ld = v;                            // 0..11
        const float4* src = &g4[(((ld * GLEN + gl) * H + h) << 4) + c4h];
        float4 v0 = __ldg(src);
        float4 v1 = __ldg(src + 8);
        float4* dst = out4 + ((long long)row << 4) + c4h;
        __stcs(dst,     v0);
        __stcs(dst + 8, v1);
        return;
    }

    // ===== e block: (ld, h, p) =====
    int eb = blk - G_BLOCKS;                   // 0..14399
    const int p  = eb % POOL;  eb /= POOL;
    const int h  = eb % H;     eb /= H;
    const int ld = eb;                          // 0..11

    const int count = d_pcount[p];             // uniform across block; <= 128
    if (count == 0) return;

    // stage pool[p,ld,e,h,:] for e=0..19 -> 320 float4 = 5KB
    __shared__ float4 s_rows[ELEN * 16];
    for (int i = tid; i < ELEN * 16; i += THREADS) {
        const int e = i >> 4;
        const int c = i & 15;
        s_rows[i] = __ldg(&pool4[((((p * 12 + ld) * ELEN + e) * H + h) << 4) + c]);
    }
    __syncthreads();

    if (tid < count) {
        // order the generic-proxy smem fill before async-proxy bulk reads
        asm volatile("fence.proxy.async.shared::cta;" ::: "memory");

        const int entry = d_plist[p * MAXENT + tid];
        const int b = entry >> 3;
        const int k = entry & 7;
        // out row base = G_ROWS + ((ld*B + b)*H + h)*100 + k*ELEN
        const long long orow =
            (long long)G_ROWS + (((long long)(ld * B + b) * H + h) * 100 + k * ELEN);
        float4* dst = out4 + (orow << 4);      // 256B-aligned, 5120B chunk

        uint32_t saddr = (uint32_t)__cvta_generic_to_shared(s_rows);
        asm volatile(
            "cp.async.bulk.global.shared::cta.bulk_group [%0], [%1], %2;"
            :: "l"(dst), "r"(saddr), "n"(CHUNK_BYTES) : "memory");
        asm volatile("cp.async.bulk.commit_group;" ::: "memory");
        // wait until the bulk op has finished READING smem (write completion
        // to gmem is ordered by kernel end for the harness's check)
        asm volatile("cp.async.bulk.wait_group.read 0;" ::: "memory");
    }
}

// ---------------------------------------------------------------------------
extern "C" void kernel_launch(void* const* d_in, const int* in_sizes, int n_in,
                              void* d_out, int out_size) {
    const float* query = (const float*)d_in[0];
    const float* gprm  = (const float*)d_in[1];
    const float* pool  = (const float*)d_in[2];
    const float* keys  = (const float*)d_in[3];
    float* out = (float*)d_out;

    // reset per-p counters (graph-capturable memset node)
    void* cnt_addr = nullptr;
    cudaGetSymbolAddress(&cnt_addr, d_pcount);
    cudaMemsetAsync(cnt_addr, 0, POOL * sizeof(int));

    // 1. top-k selection + inverse-list build
    select_topk_kernel<<<B, 512>>>((const float4*)query, (const float4*)keys);

    // 2. writer (g STG blocks + TMA bulk-store e blocks)
    write_out_kernel<<<TOTAL_BLOCKS, THREADS>>>((const float4*)gprm,
                                                (const float4*)pool,
                                                (float4*)out);
}

// round 16
// speedup vs baseline: 1.1224x; 1.1151x over previous
#include <cuda_runtime.h>
#include <cstdint>

// ---------------- problem constants ----------------
#define B      128
#define D      768
#define POOL   100
#define LG     6
#define LE     6
#define GLEN   5
#define ELEN   20
#define H      12
#define HD     64
#define TOPK   5

// Output rows: one row = HD floats = 16 float4 = 256 bytes.
#define G_ROWS     (LG*2*B*H*GLEN)              // 92,160
#define E_ROWS     (LE*2*B*H*(TOPK*ELEN))       // 1,843,200
#define G_PAIRS    (G_ROWS*8)                   // 737,280
#define E_PAIRS    (E_ROWS*8)                   // 14,745,600

#define SEL_BLOCKS 128
#define G_BLOCKS   (G_PAIRS/512)                // 1,440 (exact, 512 thr)
#define E_THREADS  256
#define E_BLOCKS   (E_PAIRS/E_THREADS)          // 57,600 (exact)

// scratch for selected indices (no cudaMalloc allowed)
__device__ int d_idx[B * TOPK];

// ---------------------------------------------------------------------------
// PDL PRIMARY: fused selection + g-region writer.
//  blocks [0,128):  selection. Publishes d_idx, __syncthreads, then TRIGGERS
//                   programmatic launch completion (~4us into the kernel).
//  blocks [128,..): g writer. Triggers IMMEDIATELY at entry (it produces
//                   nothing the secondary reads), then writes its g rows.
// => the secondary's grid-dependency grant fires as soon as the 128 sel
//    blocks publish — NOT at primary completion — so the e-drain starts
//    while g-writes are still flowing.
// ---------------------------------------------------------------------------
__global__ __launch_bounds__(512) void sel_g_kernel(
        const float4* __restrict__ query4,
        const float4* __restrict__ keys4,
        const float4* __restrict__ g4,
        float4* __restrict__ out4) {
    if (blockIdx.x >= SEL_BLOCKS) {
        // ---- g region: trigger first, then write ----
        cudaTriggerProgrammaticLaunchCompletion();
        int gid = (blockIdx.x - SEL_BLOCKS) * 512 + threadIdx.x;  // < G_PAIRS
        const int c4h = gid & 7;
        const int row = gid >> 3;
        int v  = row;
        int gl = v % GLEN; v /= GLEN;
        int h  = v % H;    v /= H;
        v >>= 7;                               // drop b
        int ld = v;                            // 0..11
        const float4* src = &g4[(((ld * GLEN + gl) * H + h) << 4) + c4h];
        float4 v0 = __ldg(src);
        float4 v1 = __ldg(src + 8);
        float4* dst = out4 + ((long long)row << 4) + c4h;
        __stcs(dst,     v0);
        __stcs(dst + 8, v1);
        return;
    }

    // ---- selection: one query row per block, 16 warps ----
    const int b    = blockIdx.x;
    const int t    = threadIdx.x;
    const int warp = t >> 5;
    const int lane = t & 31;

    __shared__ float sims[POOL];

    const float4* qr = query4 + (size_t)b * (D / 4);
    float4 fq[6];
    #pragma unroll
    for (int j = 0; j < 6; j++) fq[j] = __ldg(&qr[lane + 32 * j]);

    // qn dropped: positive per-row constant => ranking-invariant.
    for (int p = warp; p < POOL; p += 16) {
        const float4* kr = keys4 + (size_t)p * (D / 4);
        float dot = 0.f, kk = 0.f;
        #pragma unroll
        for (int j = 0; j < 6; j++) {
            float4 kv = __ldg(&kr[lane + 32 * j]);
            dot = fmaf(fq[j].x, kv.x, dot);
            dot = fmaf(fq[j].y, kv.y, dot);
            dot = fmaf(fq[j].z, kv.z, dot);
            dot = fmaf(fq[j].w, kv.w, dot);
            kk  = fmaf(kv.x, kv.x, kk);
            kk  = fmaf(kv.y, kv.y, kk);
            kk  = fmaf(kv.z, kv.z, kk);
            kk  = fmaf(kv.w, kv.w, kk);
        }
        #pragma unroll
        for (int o = 16; o > 0; o >>= 1) {
            dot += __shfl_xor_sync(0xFFFFFFFFu, dot, o);
            kk  += __shfl_xor_sync(0xFFFFFFFFu, kk,  o);
        }
        if (lane == 0) {
            float kn = fmaxf(sqrtf(kk), 1e-12f);
            sims[p] = dot / kn;
        }
    }
    __syncthreads();

    // warp 0: parallel top-5 argmax, tie-break = lowest index (jax order)
    if (warp == 0) {
        #pragma unroll
        for (int k = 0; k < TOPK; k++) {
            float best = -3.0e38f;
            int   bi   = POOL;
            #pragma unroll
            for (int j = 0; j < 4; j++) {
                int p = lane + 32 * j;
                if (p < POOL) {
                    float v = sims[p];
                    if (v > best) { best = v; bi = p; }
                }
            }
            #pragma unroll
            for (int o = 16; o > 0; o >>= 1) {
                float ov = __shfl_xor_sync(0xFFFFFFFFu, best, o);
                int   oi = __shfl_xor_sync(0xFFFFFFFFu, bi,   o);
                if (ov > best || (ov == best && oi < bi)) { best = ov; bi = oi; }
            }
            if (lane == 0) {
                d_idx[b * TOPK + k] = bi;
                sims[bi] = -3.0e38f;
            }
            __syncwarp();
        }
    }
    __syncthreads();
    // d_idx for this b is published -> allow dependents.
    cudaTriggerProgrammaticLaunchCompletion();
}

// ---------------------------------------------------------------------------
// PDL SECONDARY: e-region writer (R4's proven pattern, e rows only).
// One thread = one (row, half-slot): 2 float4 at c4h and c4h+8 of a 256B
// row; every LDG/STG covers exactly 4 full 128B lines.
//   out[ld,b,h,m,:] = pool[idx[b][m/ELEN], ld, m%ELEN, h, :]
// Each block performs one HW grid-dependency wait (satisfied ~4us after
// primary start, when all primary blocks have triggered).
// ---------------------------------------------------------------------------
__global__ __launch_bounds__(E_THREADS) void e_write_kernel(
        const float4* __restrict__ pool4,
        float4* __restrict__ out4) {
    cudaGridDependencySynchronize();

    int gid = blockIdx.x * E_THREADS + threadIdx.x;   // < E_PAIRS exact
    const int c4h = gid & 7;
    const int row = gid >> 3;              // 0..E_ROWS-1

    // row = ((ld*B + b)*H + h)*100 + m
    int v  = row;
    int m  = v % (TOPK * ELEN); v /= (TOPK * ELEN);
    int h  = v % H;             v /= H;
    int b  = v & 127;           v >>= 7;
    int ld = v;                            // 0..11
    int k  = m / ELEN;
    int e  = m - k * ELEN;
    int p  = __ldg(&d_idx[b * TOPK + k]);

    const float4* src = &pool4[((((p * 12 + ld) * ELEN + e) * H + h) << 4) + c4h];
    float4 v0 = __ldg(src);
    float4 v1 = __ldg(src + 8);

    float4* dst = out4 + (((long long)G_ROWS + row) << 4) + c4h;
    __stcs(dst,     v0);
    __stcs(dst + 8, v1);
}

// ---------------------------------------------------------------------------
extern "C" void kernel_launch(void* const* d_in, const int* in_sizes, int n_in,
                              void* d_out, int out_size) {
    const float* query = (const float*)d_in[0];
    const float* gprm  = (const float*)d_in[1];
    const float* pool  = (const float*)d_in[2];
    const float* keys  = (const float*)d_in[3];
    float* out = (float*)d_out;

    // 1. primary: fused selection + g writer (sel blocks trigger early)
    sel_g_kernel<<<SEL_BLOCKS + G_BLOCKS, 512>>>(
        (const float4*)query, (const float4*)keys,
        (const float4*)gprm, (float4*)out);

    // 2. secondary: e writer, launched with programmatic serialization so
    //    its blocks start as soon as ALL primary blocks have triggered
    //    (~4us in), overlapping the remaining g-writes.
    {
        cudaLaunchConfig_t cfg = {};
        cfg.gridDim  = dim3(E_BLOCKS);
        cfg.blockDim = dim3(E_THREADS);
        cudaLaunchAttribute attr[1];
        attr[0].id = cudaLaunchAttributeProgrammaticStreamSerialization;
        attr[0].val.programmaticStreamSerializationAllowed = 1;
        cfg.attrs    = attr;
        cfg.numAttrs = 1;
        cudaLaunchKernelEx(&cfg, e_write_kernel,
                           (const float4*)pool, (float4*)out);
    }
}